// round 4
// baseline (speedup 1.0000x reference)
#include <cuda_runtime.h>
#include <cstdint>

#define B_SZ    4
#define SEQ     4096
#define DMODEL  512
#define DINNER  1024
#define NHEADS  16
#define HD      64
#define DSTATE  64
#define CONVDIM 1152
#define DPROJ   2192
#define CHUNK   256
#define NC      16

// ---------------- scratch (static device allocations) ----------------
__device__ float g_zx[(size_t)B_SZ * SEQ * DPROJ];     // in_proj output
__device__ float g_xbc[(size_t)B_SZ * SEQ * CONVDIM];  // conv+silu output
__device__ float g_dt[(size_t)B_SZ * SEQ * NHEADS];    // softplus(dt)
__device__ float g_acum[(size_t)B_SZ * NC * NHEADS * CHUNK];       // per-chunk cumsum(dt*A)
__device__ float g_states[(size_t)B_SZ * NC * NHEADS * HD * DSTATE];
__device__ float g_prev[(size_t)B_SZ * NC * NHEADS * HD * DSTATE];
__device__ float g_y[(size_t)B_SZ * SEQ * DINNER];     // Y_diag then += Y_off + D*x
__device__ float g_yf[(size_t)B_SZ * SEQ * DINNER];    // gated + rmsnormed

// ---------------- GEMM: C[M,N] = A[M,K] * B[N,K]^T  (NT, fp32) ----------------
__global__ __launch_bounds__(256) void sgemm_nt(const float* __restrict__ A,
                                                const float* __restrict__ B,
                                                float* __restrict__ C,
                                                int M, int N, int K) {
    __shared__ float As[16][128];
    __shared__ float Bs[16][128];
    int bm = blockIdx.y * 128, bn = blockIdx.x * 128;
    int tid = threadIdx.x;
    int tx = tid & 15, ty = tid >> 4;
    float acc[8][8];
#pragma unroll
    for (int i = 0; i < 8; i++)
#pragma unroll
        for (int j = 0; j < 8; j++) acc[i][j] = 0.f;

    for (int k0 = 0; k0 < K; k0 += 16) {
#pragma unroll
        for (int i = 0; i < 2; i++) {
            int lin = tid + i * 256;          // 0..511
            int r = lin >> 2;                 // 0..127
            int c4 = (lin & 3) << 2;          // 0,4,8,12
            float4 av = *(const float4*)(A + (size_t)(bm + r) * K + k0 + c4);
            As[c4 + 0][r] = av.x; As[c4 + 1][r] = av.y;
            As[c4 + 2][r] = av.z; As[c4 + 3][r] = av.w;
            float4 bv = make_float4(0.f, 0.f, 0.f, 0.f);
            if (bn + r < N)
                bv = *(const float4*)(B + (size_t)(bn + r) * K + k0 + c4);
            Bs[c4 + 0][r] = bv.x; Bs[c4 + 1][r] = bv.y;
            Bs[c4 + 2][r] = bv.z; Bs[c4 + 3][r] = bv.w;
        }
        __syncthreads();
#pragma unroll
        for (int kk = 0; kk < 16; kk++) {
            float ar[8], br[8];
#pragma unroll
            for (int i = 0; i < 8; i++) ar[i] = As[kk][ty * 8 + i];
#pragma unroll
            for (int j = 0; j < 8; j++) br[j] = Bs[kk][tx * 8 + j];
#pragma unroll
            for (int i = 0; i < 8; i++)
#pragma unroll
                for (int j = 0; j < 8; j++) acc[i][j] = fmaf(ar[i], br[j], acc[i][j]);
        }
        __syncthreads();
    }
#pragma unroll
    for (int i = 0; i < 8; i++) {
        int row = bm + ty * 8 + i;
#pragma unroll
        for (int j = 0; j < 8; j++) {
            int col = bn + tx * 8 + j;
            if (col < N) C[(size_t)row * N + col] = acc[i][j];
        }
    }
}

// ---------------- dt = softplus(raw + bias) ----------------
__global__ void dt_kernel(const float* __restrict__ dt_bias) {
    int idx = blockIdx.x * blockDim.x + threadIdx.x;
    if (idx >= B_SZ * SEQ * NHEADS) return;
    int h = idx & (NHEADS - 1);
    int row = idx >> 4;
    float v = g_zx[(size_t)row * DPROJ + (DPROJ - NHEADS) + h] + dt_bias[h];
    g_dt[idx] = (v > 20.f) ? v : log1pf(expf(v));
}

// ---------------- causal depthwise conv (k=4) + silu ----------------
__global__ void conv_kernel(const float* __restrict__ cw, const float* __restrict__ cb) {
    int idx = blockIdx.x * blockDim.x + threadIdx.x;
    if (idx >= B_SZ * SEQ * CONVDIM) return;
    int ccol = idx % CONVDIM;
    int rl = idx / CONVDIM;
    int l = rl % SEQ;
    int b = rl / SEQ;
    float acc = cb[ccol];
#pragma unroll
    for (int k = 0; k < 4; k++) {
        int ls = l + k - 3;
        if (ls >= 0)
            acc = fmaf(g_zx[(size_t)(b * SEQ + ls) * DPROJ + DINNER + ccol],
                       cw[ccol * 4 + k], acc);
    }
    g_xbc[idx] = acc / (1.f + expf(-acc));
}

// ---------------- per-chunk inclusive scan of dt*A ----------------
__global__ void scan_kernel(const float* __restrict__ A_log) {
    __shared__ float buf[2][CHUNK];
    int h = blockIdx.x & 15;
    int t = threadIdx.x;
    int c = (blockIdx.x >> 4) & 15;
    int b = blockIdx.x >> 8;
    float Ah = -expf(A_log[h]);
    size_t row = (size_t)b * SEQ + c * CHUNK + t;
    float v = g_dt[row * NHEADS + h] * Ah;
    buf[0][t] = v;
    __syncthreads();
    int pin = 0;
#pragma unroll
    for (int off = 1; off < CHUNK; off <<= 1) {
        float x = buf[pin][t];
        if (t >= off) x += buf[pin][t - off];
        buf[pin ^ 1][t] = x;
        __syncthreads();
        pin ^= 1;
    }
    g_acum[(size_t)blockIdx.x * CHUNK + t] = buf[pin][t];
}

// ---------------- intra-chunk: Y_diag and end-of-chunk states ----------------
// block = (b,c,h); 256 threads; dynamic smem 130KB
#define CHUNK_SMEM (2 * CHUNK * HD * 4 + 2 * CHUNK * 4)
__global__ __launch_bounds__(256, 1) void chunk_kernel() {
    extern __shared__ float sm[];
    float* Bs  = sm;                     // [256][64]
    float* Xs  = sm + CHUNK * HD;        // [256][64] x*dt
    float* Ac  = sm + 2 * CHUNK * HD;    // [256]
    float* Dec = Ac + CHUNK;             // [256]
    int h = blockIdx.x & 15;
    int c = (blockIdx.x >> 4) & 15;
    int b = blockIdx.x >> 8;
    int t = threadIdx.x;
    size_t rowbase = (size_t)b * SEQ + c * CHUNK;

    for (int i = t; i < CHUNK * 16; i += 256) {
        int r = i >> 4, q = (i & 15) << 2;
        size_t rb = (rowbase + r) * CONVDIM;
        float4 bv = *(const float4*)(g_xbc + rb + DINNER + q);
        *(float4*)(Bs + r * 64 + q) = bv;
        float dtv = g_dt[(rowbase + r) * NHEADS + h];
        float4 xv = *(const float4*)(g_xbc + rb + h * HD + q);
        xv.x *= dtv; xv.y *= dtv; xv.z *= dtv; xv.w *= dtv;
        *(float4*)(Xs + r * 64 + q) = xv;
    }
    Ac[t] = g_acum[(size_t)blockIdx.x * CHUNK + t];
    __syncthreads();

    // C row in registers
    float Crow[64];
    size_t myrow = (rowbase + t) * CONVDIM + DINNER + DSTATE;
#pragma unroll
    for (int q = 0; q < 64; q += 4) {
        float4 v = *(const float4*)(g_xbc + myrow + q);
        Crow[q] = v.x; Crow[q + 1] = v.y; Crow[q + 2] = v.z; Crow[q + 3] = v.w;
    }
    float acc[64];
#pragma unroll
    for (int p = 0; p < 64; p++) acc[p] = 0.f;
    float acl = Ac[t];

    for (int s = 0; s <= t; s++) {
        const float* bs = Bs + s * 64;
        float d0 = 0.f, d1 = 0.f, d2 = 0.f, d3 = 0.f;
#pragma unroll
        for (int n = 0; n < 64; n += 4) {
            d0 = fmaf(Crow[n], bs[n], d0);
            d1 = fmaf(Crow[n + 1], bs[n + 1], d1);
            d2 = fmaf(Crow[n + 2], bs[n + 2], d2);
            d3 = fmaf(Crow[n + 3], bs[n + 3], d3);
        }
        float sc = ((d0 + d1) + (d2 + d3)) * __expf(acl - Ac[s]);
        const float* xs = Xs + s * 64;
#pragma unroll
        for (int p = 0; p < 64; p++) acc[p] = fmaf(sc, xs[p], acc[p]);
    }
    float* yo = g_y + (rowbase + t) * DINNER + h * HD;
#pragma unroll
    for (int p = 0; p < 64; p += 4) {
        float4 v = make_float4(acc[p], acc[p + 1], acc[p + 2], acc[p + 3]);
        *(float4*)(yo + p) = v;
    }

    // states[p][n] = sum_l B[l,n] * exp(Ac[255]-Ac[l]) * xdt[l,p]
    Dec[t] = __expf(Ac[CHUNK - 1] - Ac[t]);
    __syncthreads();
    int p = t & 63, nb = (t >> 6) << 4;
    float st[16];
#pragma unroll
    for (int j = 0; j < 16; j++) st[j] = 0.f;
    for (int l = 0; l < CHUNK; l++) {
        float e = Xs[l * 64 + p] * Dec[l];
        const float* bl = Bs + l * 64 + nb;
#pragma unroll
        for (int j = 0; j < 16; j++) st[j] = fmaf(e, bl[j], st[j]);
    }
    float* so = g_states + (size_t)blockIdx.x * (HD * DSTATE) + p * 64 + nb;
#pragma unroll
    for (int j = 0; j < 16; j += 4) {
        float4 v = make_float4(st[j], st[j + 1], st[j + 2], st[j + 3]);
        *(float4*)(so + j) = v;
    }
}

// ---------------- inter-chunk state recurrence (sequential over 16 chunks) ----------------
__global__ void recur_kernel() {
    int b = blockIdx.x >> 4, h = blockIdx.x & 15;
    int off = threadIdx.x * 16;
    float S[16];
#pragma unroll
    for (int j = 0; j < 16; j++) S[j] = 0.f;
    for (int c = 0; c < NC; c++) {
        int bid = (b * NC + c) * NHEADS + h;
        float e = expf(g_acum[(size_t)bid * CHUNK + CHUNK - 1]);
        float* pp = g_prev + (size_t)bid * (HD * DSTATE) + off;
        const float* ss = g_states + (size_t)bid * (HD * DSTATE) + off;
#pragma unroll
        for (int j = 0; j < 16; j++) {
            pp[j] = S[j];
            S[j] = fmaf(S[j], e, ss[j]);
        }
    }
}

// ---------------- Y_off + D*x, accumulated into g_y ----------------
__global__ __launch_bounds__(256) void yoff_kernel(const float* __restrict__ Dv) {
    __shared__ float st[HD * DSTATE];
    int h = blockIdx.x & 15;
    int c = (blockIdx.x >> 4) & 15;
    int b = blockIdx.x >> 8;
    int t = threadIdx.x;
    for (int i = t; i < (HD * DSTATE) / 4; i += 256)
        *(float4*)(st + i * 4) =
            *(const float4*)(g_prev + (size_t)blockIdx.x * (HD * DSTATE) + i * 4);
    __syncthreads();

    size_t rowbase = (size_t)b * SEQ + c * CHUNK;
    float eA = __expf(g_acum[(size_t)blockIdx.x * CHUNK + t]);
    float Crow[64];
    size_t rb = (rowbase + t) * CONVDIM;
#pragma unroll
    for (int q = 0; q < 64; q += 4) {
        float4 v = *(const float4*)(g_xbc + rb + DINNER + DSTATE + q);
        Crow[q] = v.x; Crow[q + 1] = v.y; Crow[q + 2] = v.z; Crow[q + 3] = v.w;
    }
    float Dh = Dv[h];
    const float* xh = g_xbc + rb + h * HD;
    float* yo = g_y + (rowbase + t) * DINNER + h * HD;
#pragma unroll 4
    for (int p = 0; p < 64; p++) {
        const float* sp = st + p * 64;
        float d0 = 0.f, d1 = 0.f, d2 = 0.f, d3 = 0.f;
#pragma unroll
        for (int n = 0; n < 64; n += 4) {
            d0 = fmaf(Crow[n], sp[n], d0);
            d1 = fmaf(Crow[n + 1], sp[n + 1], d1);
            d2 = fmaf(Crow[n + 2], sp[n + 2], d2);
            d3 = fmaf(Crow[n + 3], sp[n + 3], d3);
        }
        yo[p] += eA * ((d0 + d1) + (d2 + d3)) + Dh * xh[p];
    }
}

// ---------------- gate with silu(z), rmsnorm ----------------
__global__ __launch_bounds__(256) void gatenorm_kernel(const float* __restrict__ nw) {
    int row = blockIdx.x;
    int t = threadIdx.x;
    const float4* yr = (const float4*)(g_y + (size_t)row * DINNER);
    const float4* zr = (const float4*)(g_zx + (size_t)row * DPROJ);
    float4 y4 = yr[t], z4 = zr[t];
    float g0 = y4.x * (z4.x / (1.f + __expf(-z4.x)));
    float g1 = y4.y * (z4.y / (1.f + __expf(-z4.y)));
    float g2 = y4.z * (z4.z / (1.f + __expf(-z4.z)));
    float g3 = y4.w * (z4.w / (1.f + __expf(-z4.w)));
    float ss = g0 * g0 + g1 * g1 + g2 * g2 + g3 * g3;
#pragma unroll
    for (int o = 16; o > 0; o >>= 1) ss += __shfl_xor_sync(0xffffffffu, ss, o);
    __shared__ float red[8];
    if ((t & 31) == 0) red[t >> 5] = ss;
    __syncthreads();
    float tot = red[0];
#pragma unroll
    for (int w = 1; w < 8; w++) tot += red[w];
    float sc = rsqrtf(tot / (float)DINNER + 1e-5f);
    const float4* n4p = (const float4*)nw;
    float4 n4 = n4p[t];
    float4 o4 = make_float4(g0 * sc * n4.x, g1 * sc * n4.y, g2 * sc * n4.z, g3 * sc * n4.w);
    *(float4*)(g_yf + (size_t)row * DINNER + t * 4) = o4;
}

// ---------------- launcher ----------------
extern "C" void kernel_launch(void* const* d_in, const int* in_sizes, int n_in,
                              void* d_out, int out_size) {
    (void)in_sizes; (void)n_in; (void)out_size;
    const float* x     = (const float*)d_in[0];
    const float* inw   = (const float*)d_in[1];
    const float* convw = (const float*)d_in[2];
    const float* convb = (const float*)d_in[3];
    const float* dtb   = (const float*)d_in[4];
    const float* alog  = (const float*)d_in[5];
    const float* Dv    = (const float*)d_in[6];
    const float* nw    = (const float*)d_in[7];
    const float* outw  = (const float*)d_in[8];
    float* out = (float*)d_out;

    float *zx, *yf;
    cudaGetSymbolAddress((void**)&zx, g_zx);
    cudaGetSymbolAddress((void**)&yf, g_yf);
    cudaFuncSetAttribute(chunk_kernel, cudaFuncAttributeMaxDynamicSharedMemorySize,
                         CHUNK_SMEM);

    const int M = B_SZ * SEQ;  // 16384

    // 1. in_proj GEMM: zx = x @ in_proj_w^T   [16384, 2192]
    sgemm_nt<<<dim3((DPROJ + 127) / 128, M / 128), 256>>>(x, inw, zx, M, DPROJ, DMODEL);
    // 2. dt softplus
    dt_kernel<<<(B_SZ * SEQ * NHEADS + 255) / 256, 256>>>(dtb);
    // 3. conv + silu
    conv_kernel<<<(B_SZ * SEQ * CONVDIM + 255) / 256, 256>>>(convw, convb);
    // 4. per-chunk scan of dt*A
    scan_kernel<<<B_SZ * NC * NHEADS, CHUNK>>>(alog);
    // 5. intra-chunk Y_diag + states
    chunk_kernel<<<B_SZ * NC * NHEADS, 256, CHUNK_SMEM>>>();
    // 6. inter-chunk recurrence
    recur_kernel<<<B_SZ * NHEADS, 256>>>();
    // 7. Y_off + D*x
    yoff_kernel<<<B_SZ * NC * NHEADS, 256>>>(Dv);
    // 8. gate + rmsnorm
    gatenorm_kernel<<<M, 256>>>(nw);
    // 9. out_proj GEMM: out = yf @ out_proj_w^T   [16384, 512]
    sgemm_nt<<<dim3(DMODEL / 128, M / 128), 256>>>(yf, outw, out, M, DMODEL, DINNER);
}

// round 12
// speedup vs baseline: 1.1098x; 1.1098x over previous
#include <cuda_runtime.h>
#include <cstdint>

#define B_SZ    4
#define SEQ     4096
#define DMODEL  512
#define DINNER  1024
#define NHEADS  16
#define HD      64
#define DSTATE  64
#define CONVDIM 1152
#define DPROJ   2192
#define CHUNK   256
#define NC      16

// ---------------- scratch (static device allocations) ----------------
__device__ float g_zx[(size_t)B_SZ * SEQ * DPROJ];     // in_proj output
__device__ float g_xbc[(size_t)B_SZ * SEQ * CONVDIM];  // conv+silu output
__device__ float g_dt[(size_t)B_SZ * SEQ * NHEADS];    // softplus(dt)
__device__ float g_acum[(size_t)B_SZ * NC * NHEADS * CHUNK];       // per-chunk cumsum(dt*A)
__device__ float g_states[(size_t)B_SZ * NC * NHEADS * HD * DSTATE];
__device__ float g_prev[(size_t)B_SZ * NC * NHEADS * HD * DSTATE];
__device__ float g_y[(size_t)B_SZ * SEQ * DINNER];     // Y_diag then += Y_off + D*x
__device__ float g_yf[(size_t)B_SZ * SEQ * DINNER];    // gated + rmsnormed

// ---------------- tf32 helpers ----------------
__device__ __forceinline__ void f2tf32(float x, uint32_t& hi, uint32_t& lo) {
    uint32_t h;
    asm("cvt.rna.tf32.f32 %0, %1;" : "=r"(h) : "f"(x));
    float r = x - __uint_as_float(h);
    uint32_t l;
    asm("cvt.rna.tf32.f32 %0, %1;" : "=r"(l) : "f"(r));
    hi = h; lo = l;
}

__device__ __forceinline__ void mma_tf32(float* c, uint32_t a0, uint32_t a1,
                                         uint32_t a2, uint32_t a3,
                                         uint32_t b0, uint32_t b1) {
    asm volatile(
        "mma.sync.aligned.m16n8k8.row.col.f32.tf32.tf32.f32 "
        "{%0,%1,%2,%3},{%4,%5,%6,%7},{%8,%9},{%0,%1,%2,%3};"
        : "+f"(c[0]), "+f"(c[1]), "+f"(c[2]), "+f"(c[3])
        : "r"(a0), "r"(a1), "r"(a2), "r"(a3), "r"(b0), "r"(b1));
}

// ---------------- tensor GEMM: C[M,N] = A[M,K] * B[N,K]^T (3xTF32 split) ----------------
// block tile 128x128, K-tile 32; 8 warps, each 64(M) x 32(N).
#define LDP 132  // padded row to avoid smem bank conflicts
__global__ __launch_bounds__(256, 1) void tgemm_nt(const float* __restrict__ A,
                                                   const float* __restrict__ B,
                                                   float* __restrict__ C,
                                                   int M, int N, int K) {
    __shared__ float As[32][LDP];
    __shared__ float Bs[32][LDP];
    int bm = blockIdx.y * 128, bn = blockIdx.x * 128;
    int tid = threadIdx.x;
    int wid = tid >> 5, lane = tid & 31;
    int group = lane >> 2, tig = lane & 3;
    int warpM = (wid & 1) * 64;   // 2 warps over M
    int warpN = (wid >> 1) * 32;  // 4 warps over N

    float acc[4][4][4];  // [mt][nt][frag]
#pragma unroll
    for (int mt = 0; mt < 4; mt++)
#pragma unroll
        for (int nt = 0; nt < 4; nt++)
#pragma unroll
            for (int j = 0; j < 4; j++) acc[mt][nt][j] = 0.f;

    for (int k0 = 0; k0 < K; k0 += 32) {
        // load A/B tiles k-major (transposed) into smem
#pragma unroll
        for (int i = 0; i < 4; i++) {
            int lin = tid + i * 256;       // 0..1023
            int r = lin >> 3;              // 0..127
            int c4 = (lin & 7) << 2;       // 0..28 step 4
            float4 av = *(const float4*)(A + (size_t)(bm + r) * K + k0 + c4);
            As[c4 + 0][r] = av.x; As[c4 + 1][r] = av.y;
            As[c4 + 2][r] = av.z; As[c4 + 3][r] = av.w;
            float4 bv = make_float4(0.f, 0.f, 0.f, 0.f);
            if (bn + r < N)
                bv = *(const float4*)(B + (size_t)(bn + r) * K + k0 + c4);
            Bs[c4 + 0][r] = bv.x; Bs[c4 + 1][r] = bv.y;
            Bs[c4 + 2][r] = bv.z; Bs[c4 + 3][r] = bv.w;
        }
        __syncthreads();

#pragma unroll
        for (int k8 = 0; k8 < 4; k8++) {
            int kb = k8 * 8;
            uint32_t ah[4][4], al[4][4], bh[4][2], bl[4][2];
#pragma unroll
            for (int mt = 0; mt < 4; mt++) {
                int m0 = warpM + mt * 16 + group;
                f2tf32(As[kb + tig][m0],         ah[mt][0], al[mt][0]);
                f2tf32(As[kb + tig][m0 + 8],     ah[mt][1], al[mt][1]);
                f2tf32(As[kb + tig + 4][m0],     ah[mt][2], al[mt][2]);
                f2tf32(As[kb + tig + 4][m0 + 8], ah[mt][3], al[mt][3]);
            }
#pragma unroll
            for (int nt = 0; nt < 4; nt++) {
                int n0 = warpN + nt * 8 + group;
                f2tf32(Bs[kb + tig][n0],     bh[nt][0], bl[nt][0]);
                f2tf32(Bs[kb + tig + 4][n0], bh[nt][1], bl[nt][1]);
            }
#pragma unroll
            for (int mt = 0; mt < 4; mt++)
#pragma unroll
                for (int nt = 0; nt < 4; nt++) {
                    float* c = acc[mt][nt];
                    mma_tf32(c, ah[mt][0], ah[mt][1], ah[mt][2], ah[mt][3],
                             bh[nt][0], bh[nt][1]);
                    mma_tf32(c, al[mt][0], al[mt][1], al[mt][2], al[mt][3],
                             bh[nt][0], bh[nt][1]);
                    mma_tf32(c, ah[mt][0], ah[mt][1], ah[mt][2], ah[mt][3],
                             bl[nt][0], bl[nt][1]);
                }
        }
        __syncthreads();
    }

    // epilogue
#pragma unroll
    for (int mt = 0; mt < 4; mt++) {
        int row0 = bm + warpM + mt * 16 + group;
#pragma unroll
        for (int nt = 0; nt < 4; nt++) {
            int col = bn + warpN + nt * 8 + 2 * tig;
            if (col < N) {
                float2 v01 = make_float2(acc[mt][nt][0], acc[mt][nt][1]);
                float2 v23 = make_float2(acc[mt][nt][2], acc[mt][nt][3]);
                *(float2*)(C + (size_t)row0 * N + col) = v01;
                *(float2*)(C + (size_t)(row0 + 8) * N + col) = v23;
            }
        }
    }
}

// ---------------- dt = softplus(raw + bias) ----------------
__global__ void dt_kernel(const float* __restrict__ dt_bias) {
    int idx = blockIdx.x * blockDim.x + threadIdx.x;
    if (idx >= B_SZ * SEQ * NHEADS) return;
    int h = idx & (NHEADS - 1);
    int row = idx >> 4;
    float v = g_zx[(size_t)row * DPROJ + (DPROJ - NHEADS) + h] + dt_bias[h];
    g_dt[idx] = (v > 20.f) ? v : log1pf(expf(v));
}

// ---------------- causal depthwise conv (k=4) + silu ----------------
__global__ void conv_kernel(const float* __restrict__ cw, const float* __restrict__ cb) {
    int idx = blockIdx.x * blockDim.x + threadIdx.x;
    if (idx >= B_SZ * SEQ * CONVDIM) return;
    int ccol = idx % CONVDIM;
    int rl = idx / CONVDIM;
    int l = rl % SEQ;
    int b = rl / SEQ;
    float acc = cb[ccol];
#pragma unroll
    for (int k = 0; k < 4; k++) {
        int ls = l + k - 3;
        if (ls >= 0)
            acc = fmaf(g_zx[(size_t)(b * SEQ + ls) * DPROJ + DINNER + ccol],
                       cw[ccol * 4 + k], acc);
    }
    g_xbc[idx] = acc / (1.f + expf(-acc));
}

// ---------------- per-chunk inclusive scan of dt*A ----------------
__global__ void scan_kernel(const float* __restrict__ A_log) {
    __shared__ float buf[2][CHUNK];
    int h = blockIdx.x & 15;
    int t = threadIdx.x;
    int c = (blockIdx.x >> 4) & 15;
    int b = blockIdx.x >> 8;
    float Ah = -expf(A_log[h]);
    size_t row = (size_t)b * SEQ + c * CHUNK + t;
    float v = g_dt[row * NHEADS + h] * Ah;
    buf[0][t] = v;
    __syncthreads();
    int pin = 0;
#pragma unroll
    for (int off = 1; off < CHUNK; off <<= 1) {
        float x = buf[pin][t];
        if (t >= off) x += buf[pin][t - off];
        buf[pin ^ 1][t] = x;
        __syncthreads();
        pin ^= 1;
    }
    g_acum[(size_t)blockIdx.x * CHUNK + t] = buf[pin][t];
}

// ---------------- intra-chunk: Y_diag and end-of-chunk states ----------------
#define CHUNK_SMEM (2 * CHUNK * HD * 4 + 2 * CHUNK * 4)
__global__ __launch_bounds__(256, 1) void chunk_kernel() {
    extern __shared__ float sm[];
    float* Bs  = sm;                     // [256][64]
    float* Xs  = sm + CHUNK * HD;        // [256][64] x*dt
    float* Ac  = sm + 2 * CHUNK * HD;    // [256]
    float* Dec = Ac + CHUNK;             // [256]
    int h = blockIdx.x & 15;
    int c = (blockIdx.x >> 4) & 15;
    int b = blockIdx.x >> 8;
    int t = threadIdx.x;
    size_t rowbase = (size_t)b * SEQ + c * CHUNK;

    for (int i = t; i < CHUNK * 16; i += 256) {
        int r = i >> 4, q = (i & 15) << 2;
        size_t rb = (rowbase + r) * CONVDIM;
        float4 bv = *(const float4*)(g_xbc + rb + DINNER + q);
        *(float4*)(Bs + r * 64 + q) = bv;
        float dtv = g_dt[(rowbase + r) * NHEADS + h];
        float4 xv = *(const float4*)(g_xbc + rb + h * HD + q);
        xv.x *= dtv; xv.y *= dtv; xv.z *= dtv; xv.w *= dtv;
        *(float4*)(Xs + r * 64 + q) = xv;
    }
    Ac[t] = g_acum[(size_t)blockIdx.x * CHUNK + t];
    __syncthreads();

    float Crow[64];
    size_t myrow = (rowbase + t) * CONVDIM + DINNER + DSTATE;
#pragma unroll
    for (int q = 0; q < 64; q += 4) {
        float4 v = *(const float4*)(g_xbc + myrow + q);
        Crow[q] = v.x; Crow[q + 1] = v.y; Crow[q + 2] = v.z; Crow[q + 3] = v.w;
    }
    float acc[64];
#pragma unroll
    for (int p = 0; p < 64; p++) acc[p] = 0.f;
    float acl = Ac[t];

    for (int s = 0; s <= t; s++) {
        const float* bs = Bs + s * 64;
        float d0 = 0.f, d1 = 0.f, d2 = 0.f, d3 = 0.f;
#pragma unroll
        for (int n = 0; n < 64; n += 4) {
            d0 = fmaf(Crow[n], bs[n], d0);
            d1 = fmaf(Crow[n + 1], bs[n + 1], d1);
            d2 = fmaf(Crow[n + 2], bs[n + 2], d2);
            d3 = fmaf(Crow[n + 3], bs[n + 3], d3);
        }
        float sc = ((d0 + d1) + (d2 + d3)) * __expf(acl - Ac[s]);
        const float* xs = Xs + s * 64;
#pragma unroll
        for (int p = 0; p < 64; p++) acc[p] = fmaf(sc, xs[p], acc[p]);
    }
    float* yo = g_y + (rowbase + t) * DINNER + h * HD;
#pragma unroll
    for (int p = 0; p < 64; p += 4) {
        float4 v = make_float4(acc[p], acc[p + 1], acc[p + 2], acc[p + 3]);
        *(float4*)(yo + p) = v;
    }

    Dec[t] = __expf(Ac[CHUNK - 1] - Ac[t]);
    __syncthreads();
    int p = t & 63, nb = (t >> 6) << 4;
    float st[16];
#pragma unroll
    for (int j = 0; j < 16; j++) st[j] = 0.f;
    for (int l = 0; l < CHUNK; l++) {
        float e = Xs[l * 64 + p] * Dec[l];
        const float* bl = Bs + l * 64 + nb;
#pragma unroll
        for (int j = 0; j < 16; j++) st[j] = fmaf(e, bl[j], st[j]);
    }
    float* so = g_states + (size_t)blockIdx.x * (HD * DSTATE) + p * 64 + nb;
#pragma unroll
    for (int j = 0; j < 16; j += 4) {
        float4 v = make_float4(st[j], st[j + 1], st[j + 2], st[j + 3]);
        *(float4*)(so + j) = v;
    }
}

// ---------------- inter-chunk state recurrence ----------------
__global__ void recur_kernel() {
    int b = blockIdx.x >> 4, h = blockIdx.x & 15;
    int off = threadIdx.x * 16;
    float S[16];
#pragma unroll
    for (int j = 0; j < 16; j++) S[j] = 0.f;
    for (int c = 0; c < NC; c++) {
        int bid = (b * NC + c) * NHEADS + h;
        float e = expf(g_acum[(size_t)bid * CHUNK + CHUNK - 1]);
        float* pp = g_prev + (size_t)bid * (HD * DSTATE) + off;
        const float* ss = g_states + (size_t)bid * (HD * DSTATE) + off;
#pragma unroll
        for (int j = 0; j < 16; j++) {
            pp[j] = S[j];
            S[j] = fmaf(S[j], e, ss[j]);
        }
    }
}

// ---------------- Y_off + D*x, accumulated into g_y ----------------
__global__ __launch_bounds__(256) void yoff_kernel(const float* __restrict__ Dv) {
    __shared__ float st[HD * DSTATE];
    int h = blockIdx.x & 15;
    int c = (blockIdx.x >> 4) & 15;
    int b = blockIdx.x >> 8;
    int t = threadIdx.x;
    for (int i = t; i < (HD * DSTATE) / 4; i += 256)
        *(float4*)(st + i * 4) =
            *(const float4*)(g_prev + (size_t)blockIdx.x * (HD * DSTATE) + i * 4);
    __syncthreads();

    size_t rowbase = (size_t)b * SEQ + c * CHUNK;
    float eA = __expf(g_acum[(size_t)blockIdx.x * CHUNK + t]);
    float Crow[64];
    size_t rb = (rowbase + t) * CONVDIM;
#pragma unroll
    for (int q = 0; q < 64; q += 4) {
        float4 v = *(const float4*)(g_xbc + rb + DINNER + DSTATE + q);
        Crow[q] = v.x; Crow[q + 1] = v.y; Crow[q + 2] = v.z; Crow[q + 3] = v.w;
    }
    float Dh = Dv[h];
    const float* xh = g_xbc + rb + h * HD;
    float* yo = g_y + (rowbase + t) * DINNER + h * HD;
#pragma unroll 4
    for (int p = 0; p < 64; p++) {
        const float* sp = st + p * 64;
        float d0 = 0.f, d1 = 0.f, d2 = 0.f, d3 = 0.f;
#pragma unroll
        for (int n = 0; n < 64; n += 4) {
            d0 = fmaf(Crow[n], sp[n], d0);
            d1 = fmaf(Crow[n + 1], sp[n + 1], d1);
            d2 = fmaf(Crow[n + 2], sp[n + 2], d2);
            d3 = fmaf(Crow[n + 3], sp[n + 3], d3);
        }
        yo[p] += eA * ((d0 + d1) + (d2 + d3)) + Dh * xh[p];
    }
}

// ---------------- gate with silu(z), rmsnorm ----------------
__global__ __launch_bounds__(256) void gatenorm_kernel(const float* __restrict__ nw) {
    int row = blockIdx.x;
    int t = threadIdx.x;
    const float4* yr = (const float4*)(g_y + (size_t)row * DINNER);
    const float4* zr = (const float4*)(g_zx + (size_t)row * DPROJ);
    float4 y4 = yr[t], z4 = zr[t];
    float g0 = y4.x * (z4.x / (1.f + __expf(-z4.x)));
    float g1 = y4.y * (z4.y / (1.f + __expf(-z4.y)));
    float g2 = y4.z * (z4.z / (1.f + __expf(-z4.z)));
    float g3 = y4.w * (z4.w / (1.f + __expf(-z4.w)));
    float ss = g0 * g0 + g1 * g1 + g2 * g2 + g3 * g3;
#pragma unroll
    for (int o = 16; o > 0; o >>= 1) ss += __shfl_xor_sync(0xffffffffu, ss, o);
    __shared__ float red[8];
    if ((t & 31) == 0) red[t >> 5] = ss;
    __syncthreads();
    float tot = red[0];
#pragma unroll
    for (int w = 1; w < 8; w++) tot += red[w];
    float sc = rsqrtf(tot / (float)DINNER + 1e-5f);
    const float4* n4p = (const float4*)nw;
    float4 n4 = n4p[t];
    float4 o4 = make_float4(g0 * sc * n4.x, g1 * sc * n4.y, g2 * sc * n4.z, g3 * sc * n4.w);
    *(float4*)(g_yf + (size_t)row * DINNER + t * 4) = o4;
}

// ---------------- launcher ----------------
extern "C" void kernel_launch(void* const* d_in, const int* in_sizes, int n_in,
                              void* d_out, int out_size) {
    (void)in_sizes; (void)n_in; (void)out_size;
    const float* x     = (const float*)d_in[0];
    const float* inw   = (const float*)d_in[1];
    const float* convw = (const float*)d_in[2];
    const float* convb = (const float*)d_in[3];
    const float* dtb   = (const float*)d_in[4];
    const float* alog  = (const float*)d_in[5];
    const float* Dv    = (const float*)d_in[6];
    const float* nw    = (const float*)d_in[7];
    const float* outw  = (const float*)d_in[8];
    float* out = (float*)d_out;

    float *zx, *yf;
    cudaGetSymbolAddress((void**)&zx, g_zx);
    cudaGetSymbolAddress((void**)&yf, g_yf);
    cudaFuncSetAttribute(chunk_kernel, cudaFuncAttributeMaxDynamicSharedMemorySize,
                         CHUNK_SMEM);

    const int M = B_SZ * SEQ;  // 16384

    // 1. in_proj GEMM: zx = x @ in_proj_w^T   [16384, 2192]
    tgemm_nt<<<dim3((DPROJ + 127) / 128, M / 128), 256>>>(x, inw, zx, M, DPROJ, DMODEL);
    // 2. dt softplus
    dt_kernel<<<(B_SZ * SEQ * NHEADS + 255) / 256, 256>>>(dtb);
    // 3. conv + silu
    conv_kernel<<<(B_SZ * SEQ * CONVDIM + 255) / 256, 256>>>(convw, convb);
    // 4. per-chunk scan of dt*A
    scan_kernel<<<B_SZ * NC * NHEADS, CHUNK>>>(alog);
    // 5. intra-chunk Y_diag + states
    chunk_kernel<<<B_SZ * NC * NHEADS, 256, CHUNK_SMEM>>>();
    // 6. inter-chunk recurrence
    recur_kernel<<<B_SZ * NHEADS, 256>>>();
    // 7. Y_off + D*x
    yoff_kernel<<<B_SZ * NC * NHEADS, 256>>>(Dv);
    // 8. gate + rmsnorm
    gatenorm_kernel<<<M, 256>>>(nw);
    // 9. out_proj GEMM: out = yf @ out_proj_w^T   [16384, 512]
    tgemm_nt<<<dim3(DMODEL / 128, M / 128), 256>>>(yf, outw, out, M, DMODEL, DINNER);
}

// round 13
// speedup vs baseline: 1.2847x; 1.1576x over previous
#include <cuda_runtime.h>
#include <cuda_bf16.h>
#include <cstdint>

#define B_SZ    4
#define SEQ     4096
#define DMODEL  512
#define DINNER  1024
#define NHEADS  16
#define HD      64
#define DSTATE  64
#define CONVDIM 1152
#define DPROJ   2192
#define CHUNK   256
#define NC      16

// ---------------- scratch (static device allocations) ----------------
__device__ float g_zx[(size_t)B_SZ * SEQ * DPROJ];     // in_proj output
__device__ float g_xbc[(size_t)B_SZ * SEQ * CONVDIM];  // conv+silu output
__device__ float g_dt[(size_t)B_SZ * SEQ * NHEADS];    // softplus(dt)
__device__ float g_acum[(size_t)B_SZ * NC * NHEADS * CHUNK];       // per-chunk cumsum(dt*A)
__device__ float g_states[(size_t)B_SZ * NC * NHEADS * HD * DSTATE];
__device__ float g_prev[(size_t)B_SZ * NC * NHEADS * HD * DSTATE];
__device__ float g_y[(size_t)B_SZ * SEQ * DINNER];     // Y_diag then += Y_off + D*x
__device__ float g_yf[(size_t)B_SZ * SEQ * DINNER];    // gated + rmsnormed

// ---------------- bf16 split helpers ----------------
// pack two floats into (hi, lo) bf16x2 pairs: x = hi + lo to ~16 mantissa bits
__device__ __forceinline__ void cvt2_bf16(float a, float b, uint32_t& hi, uint32_t& lo) {
    __nv_bfloat16 ah = __float2bfloat16_rn(a);
    __nv_bfloat16 bh = __float2bfloat16_rn(b);
    __nv_bfloat16 al = __float2bfloat16_rn(a - __bfloat162float(ah));
    __nv_bfloat16 bl = __float2bfloat16_rn(b - __bfloat162float(bh));
    hi = ((uint32_t)__bfloat16_as_ushort(bh) << 16) | (uint32_t)__bfloat16_as_ushort(ah);
    lo = ((uint32_t)__bfloat16_as_ushort(bl) << 16) | (uint32_t)__bfloat16_as_ushort(al);
}

__device__ __forceinline__ void mma_bf16(float* c, uint32_t a0, uint32_t a1,
                                         uint32_t a2, uint32_t a3,
                                         uint32_t b0, uint32_t b1) {
    asm volatile(
        "mma.sync.aligned.m16n8k16.row.col.f32.bf16.bf16.f32 "
        "{%0,%1,%2,%3},{%4,%5,%6,%7},{%8,%9},{%0,%1,%2,%3};"
        : "+f"(c[0]), "+f"(c[1]), "+f"(c[2]), "+f"(c[3])
        : "r"(a0), "r"(a1), "r"(a2), "r"(a3), "r"(b0), "r"(b1));
}

// ---------------- tensor GEMM: C[M,N] = A[M,K] * B[N,K]^T (3x bf16 split) ----------------
// block tile 128x128, K-tile 32; 8 warps, each 64(M) x 32(N). smem holds packed
// bf16 k-pairs (hi/lo), converted once at fill time.
#define LDPW 132
__global__ __launch_bounds__(256, 1) void tgemm_nt(const float* __restrict__ A,
                                                   const float* __restrict__ B,
                                                   float* __restrict__ C,
                                                   int M, int N, int K) {
    __shared__ uint32_t Ahi[16][LDPW], Alo[16][LDPW];
    __shared__ uint32_t Bhi[16][LDPW], Blo[16][LDPW];
    int bm = blockIdx.y * 128, bn = blockIdx.x * 128;
    int tid = threadIdx.x;
    int wid = tid >> 5, lane = tid & 31;
    int group = lane >> 2, tig = lane & 3;
    int warpM = (wid & 1) * 64;   // 2 warps over M
    int warpN = (wid >> 1) * 32;  // 4 warps over N

    float acc[4][4][4];  // [mt][nt][frag]
#pragma unroll
    for (int mt = 0; mt < 4; mt++)
#pragma unroll
        for (int nt = 0; nt < 4; nt++)
#pragma unroll
            for (int j = 0; j < 4; j++) acc[mt][nt][j] = 0.f;

    for (int k0 = 0; k0 < K; k0 += 32) {
        // fill: convert fp32 -> packed bf16 hi/lo k-pairs, transposed [kpair][row]
#pragma unroll
        for (int i = 0; i < 4; i++) {
            int lin = tid + i * 256;       // 0..1023
            int r = lin >> 3;              // 0..127
            int c4 = (lin & 7) << 2;       // k offset 0..28 step 4
            int p0 = c4 >> 1;              // k-pair row 0..14 step 2
            float4 av = *(const float4*)(A + (size_t)(bm + r) * K + k0 + c4);
            cvt2_bf16(av.x, av.y, Ahi[p0][r], Alo[p0][r]);
            cvt2_bf16(av.z, av.w, Ahi[p0 + 1][r], Alo[p0 + 1][r]);
            float4 bv = make_float4(0.f, 0.f, 0.f, 0.f);
            if (bn + r < N)
                bv = *(const float4*)(B + (size_t)(bn + r) * K + k0 + c4);
            cvt2_bf16(bv.x, bv.y, Bhi[p0][r], Blo[p0][r]);
            cvt2_bf16(bv.z, bv.w, Bhi[p0 + 1][r], Blo[p0 + 1][r]);
        }
        __syncthreads();

#pragma unroll
        for (int k16 = 0; k16 < 2; k16++) {
            int kb2 = k16 * 8;  // k-pair base (8 pairs = 16 k)
            uint32_t ah[4][4], al[4][4], bh[4][2], bl[4][2];
#pragma unroll
            for (int mt = 0; mt < 4; mt++) {
                int m0 = warpM + mt * 16 + group;
                ah[mt][0] = Ahi[kb2 + tig][m0];
                ah[mt][1] = Ahi[kb2 + tig][m0 + 8];
                ah[mt][2] = Ahi[kb2 + tig + 4][m0];
                ah[mt][3] = Ahi[kb2 + tig + 4][m0 + 8];
                al[mt][0] = Alo[kb2 + tig][m0];
                al[mt][1] = Alo[kb2 + tig][m0 + 8];
                al[mt][2] = Alo[kb2 + tig + 4][m0];
                al[mt][3] = Alo[kb2 + tig + 4][m0 + 8];
            }
#pragma unroll
            for (int nt = 0; nt < 4; nt++) {
                int n0 = warpN + nt * 8 + group;
                bh[nt][0] = Bhi[kb2 + tig][n0];
                bh[nt][1] = Bhi[kb2 + tig + 4][n0];
                bl[nt][0] = Blo[kb2 + tig][n0];
                bl[nt][1] = Blo[kb2 + tig + 4][n0];
            }
#pragma unroll
            for (int mt = 0; mt < 4; mt++)
#pragma unroll
                for (int nt = 0; nt < 4; nt++) {
                    float* c = acc[mt][nt];
                    mma_bf16(c, ah[mt][0], ah[mt][1], ah[mt][2], ah[mt][3],
                             bh[nt][0], bh[nt][1]);
                    mma_bf16(c, al[mt][0], al[mt][1], al[mt][2], al[mt][3],
                             bh[nt][0], bh[nt][1]);
                    mma_bf16(c, ah[mt][0], ah[mt][1], ah[mt][2], ah[mt][3],
                             bl[nt][0], bl[nt][1]);
                }
        }
        __syncthreads();
    }

    // epilogue (m16n8 C layout: c0,c1 -> row group; c2,c3 -> row group+8)
#pragma unroll
    for (int mt = 0; mt < 4; mt++) {
        int row0 = bm + warpM + mt * 16 + group;
#pragma unroll
        for (int nt = 0; nt < 4; nt++) {
            int col = bn + warpN + nt * 8 + 2 * tig;
            if (col < N) {
                float2 v01 = make_float2(acc[mt][nt][0], acc[mt][nt][1]);
                float2 v23 = make_float2(acc[mt][nt][2], acc[mt][nt][3]);
                *(float2*)(C + (size_t)row0 * N + col) = v01;
                *(float2*)(C + (size_t)(row0 + 8) * N + col) = v23;
            }
        }
    }
}

// ---------------- dt = softplus(x @ w_dt^T + bias), exact fp32 ----------------
// one block per sequence row; warp w computes head h = w
__global__ __launch_bounds__(512) void dt_kernel(const float* __restrict__ x,
                                                 const float* __restrict__ inw,
                                                 const float* __restrict__ dt_bias) {
    int row = blockIdx.x;
    int h = threadIdx.x >> 5;
    int lane = threadIdx.x & 31;
    const float* xr = x + (size_t)row * DMODEL;
    const float* wr = inw + (size_t)(DPROJ - NHEADS + h) * DMODEL;
    float s = 0.f;
#pragma unroll
    for (int k = 0; k < DMODEL / 32; k++)
        s = fmaf(xr[lane + k * 32], wr[lane + k * 32], s);
#pragma unroll
    for (int o = 16; o > 0; o >>= 1) s += __shfl_xor_sync(0xffffffffu, s, o);
    if (lane == 0) {
        float v = s + dt_bias[h];
        g_dt[(size_t)row * NHEADS + h] = (v > 20.f) ? v : log1pf(expf(v));
    }
}

// ---------------- causal depthwise conv (k=4) + silu ----------------
__global__ void conv_kernel(const float* __restrict__ cw, const float* __restrict__ cb) {
    int idx = blockIdx.x * blockDim.x + threadIdx.x;
    if (idx >= B_SZ * SEQ * CONVDIM) return;
    int ccol = idx % CONVDIM;
    int rl = idx / CONVDIM;
    int l = rl % SEQ;
    int b = rl / SEQ;
    float acc = cb[ccol];
#pragma unroll
    for (int k = 0; k < 4; k++) {
        int ls = l + k - 3;
        if (ls >= 0)
            acc = fmaf(g_zx[(size_t)(b * SEQ + ls) * DPROJ + DINNER + ccol],
                       cw[ccol * 4 + k], acc);
    }
    g_xbc[idx] = acc / (1.f + expf(-acc));
}

// ---------------- per-chunk inclusive scan of dt*A ----------------
__global__ void scan_kernel(const float* __restrict__ A_log) {
    __shared__ float buf[2][CHUNK];
    int h = blockIdx.x & 15;
    int t = threadIdx.x;
    int c = (blockIdx.x >> 4) & 15;
    int b = blockIdx.x >> 8;
    float Ah = -expf(A_log[h]);
    size_t row = (size_t)b * SEQ + c * CHUNK + t;
    float v = g_dt[row * NHEADS + h] * Ah;
    buf[0][t] = v;
    __syncthreads();
    int pin = 0;
#pragma unroll
    for (int off = 1; off < CHUNK; off <<= 1) {
        float x = buf[pin][t];
        if (t >= off) x += buf[pin][t - off];
        buf[pin ^ 1][t] = x;
        __syncthreads();
        pin ^= 1;
    }
    g_acum[(size_t)blockIdx.x * CHUNK + t] = buf[pin][t];
}

// ---------------- intra-chunk: Y_diag and end-of-chunk states ----------------
#define CHUNK_SMEM (2 * CHUNK * HD * 4 + 2 * CHUNK * 4)
__global__ __launch_bounds__(256, 1) void chunk_kernel() {
    extern __shared__ float sm[];
    float* Bs  = sm;                     // [256][64]
    float* Xs  = sm + CHUNK * HD;        // [256][64] x*dt
    float* Ac  = sm + 2 * CHUNK * HD;    // [256]
    float* Dec = Ac + CHUNK;             // [256]
    int h = blockIdx.x & 15;
    int c = (blockIdx.x >> 4) & 15;
    int b = blockIdx.x >> 8;
    int t = threadIdx.x;
    size_t rowbase = (size_t)b * SEQ + c * CHUNK;

    for (int i = t; i < CHUNK * 16; i += 256) {
        int r = i >> 4, q = (i & 15) << 2;
        size_t rb = (rowbase + r) * CONVDIM;
        float4 bv = *(const float4*)(g_xbc + rb + DINNER + q);
        *(float4*)(Bs + r * 64 + q) = bv;
        float dtv = g_dt[(rowbase + r) * NHEADS + h];
        float4 xv = *(const float4*)(g_xbc + rb + h * HD + q);
        xv.x *= dtv; xv.y *= dtv; xv.z *= dtv; xv.w *= dtv;
        *(float4*)(Xs + r * 64 + q) = xv;
    }
    Ac[t] = g_acum[(size_t)blockIdx.x * CHUNK + t];
    __syncthreads();

    float Crow[64];
    size_t myrow = (rowbase + t) * CONVDIM + DINNER + DSTATE;
#pragma unroll
    for (int q = 0; q < 64; q += 4) {
        float4 v = *(const float4*)(g_xbc + myrow + q);
        Crow[q] = v.x; Crow[q + 1] = v.y; Crow[q + 2] = v.z; Crow[q + 3] = v.w;
    }
    float acc[64];
#pragma unroll
    for (int p = 0; p < 64; p++) acc[p] = 0.f;
    float acl = Ac[t];

    for (int s = 0; s <= t; s++) {
        const float* bs = Bs + s * 64;
        float d0 = 0.f, d1 = 0.f, d2 = 0.f, d3 = 0.f;
#pragma unroll
        for (int n = 0; n < 64; n += 4) {
            d0 = fmaf(Crow[n], bs[n], d0);
            d1 = fmaf(Crow[n + 1], bs[n + 1], d1);
            d2 = fmaf(Crow[n + 2], bs[n + 2], d2);
            d3 = fmaf(Crow[n + 3], bs[n + 3], d3);
        }
        float sc = ((d0 + d1) + (d2 + d3)) * __expf(acl - Ac[s]);
        const float* xs = Xs + s * 64;
#pragma unroll
        for (int p = 0; p < 64; p++) acc[p] = fmaf(sc, xs[p], acc[p]);
    }
    float* yo = g_y + (rowbase + t) * DINNER + h * HD;
#pragma unroll
    for (int p = 0; p < 64; p += 4) {
        float4 v = make_float4(acc[p], acc[p + 1], acc[p + 2], acc[p + 3]);
        *(float4*)(yo + p) = v;
    }

    Dec[t] = __expf(Ac[CHUNK - 1] - Ac[t]);
    __syncthreads();
    int p = t & 63, nb = (t >> 6) << 4;
    float st[16];
#pragma unroll
    for (int j = 0; j < 16; j++) st[j] = 0.f;
    for (int l = 0; l < CHUNK; l++) {
        float e = Xs[l * 64 + p] * Dec[l];
        const float* bl = Bs + l * 64 + nb;
#pragma unroll
        for (int j = 0; j < 16; j++) st[j] = fmaf(e, bl[j], st[j]);
    }
    float* so = g_states + (size_t)blockIdx.x * (HD * DSTATE) + p * 64 + nb;
#pragma unroll
    for (int j = 0; j < 16; j += 4) {
        float4 v = make_float4(st[j], st[j + 1], st[j + 2], st[j + 3]);
        *(float4*)(so + j) = v;
    }
}

// ---------------- inter-chunk state recurrence ----------------
__global__ void recur_kernel() {
    int b = blockIdx.x >> 4, h = blockIdx.x & 15;
    int off = threadIdx.x * 16;
    float S[16];
#pragma unroll
    for (int j = 0; j < 16; j++) S[j] = 0.f;
    for (int c = 0; c < NC; c++) {
        int bid = (b * NC + c) * NHEADS + h;
        float e = expf(g_acum[(size_t)bid * CHUNK + CHUNK - 1]);
        float* pp = g_prev + (size_t)bid * (HD * DSTATE) + off;
        const float* ss = g_states + (size_t)bid * (HD * DSTATE) + off;
#pragma unroll
        for (int j = 0; j < 16; j++) {
            pp[j] = S[j];
            S[j] = fmaf(S[j], e, ss[j]);
        }
    }
}

// ---------------- Y_off + D*x, accumulated into g_y ----------------
__global__ __launch_bounds__(256) void yoff_kernel(const float* __restrict__ Dv) {
    __shared__ float st[HD * DSTATE];
    int h = blockIdx.x & 15;
    int c = (blockIdx.x >> 4) & 15;
    int b = blockIdx.x >> 8;
    int t = threadIdx.x;
    for (int i = t; i < (HD * DSTATE) / 4; i += 256)
        *(float4*)(st + i * 4) =
            *(const float4*)(g_prev + (size_t)blockIdx.x * (HD * DSTATE) + i * 4);
    __syncthreads();

    size_t rowbase = (size_t)b * SEQ + c * CHUNK;
    float eA = __expf(g_acum[(size_t)blockIdx.x * CHUNK + t]);
    float Crow[64];
    size_t rb = (rowbase + t) * CONVDIM;
#pragma unroll
    for (int q = 0; q < 64; q += 4) {
        float4 v = *(const float4*)(g_xbc + rb + DINNER + DSTATE + q);
        Crow[q] = v.x; Crow[q + 1] = v.y; Crow[q + 2] = v.z; Crow[q + 3] = v.w;
    }
    float Dh = Dv[h];
    const float* xh = g_xbc + rb + h * HD;
    float* yo = g_y + (rowbase + t) * DINNER + h * HD;
#pragma unroll 4
    for (int p = 0; p < 64; p++) {
        const float* sp = st + p * 64;
        float d0 = 0.f, d1 = 0.f, d2 = 0.f, d3 = 0.f;
#pragma unroll
        for (int n = 0; n < 64; n += 4) {
            d0 = fmaf(Crow[n], sp[n], d0);
            d1 = fmaf(Crow[n + 1], sp[n + 1], d1);
            d2 = fmaf(Crow[n + 2], sp[n + 2], d2);
            d3 = fmaf(Crow[n + 3], sp[n + 3], d3);
        }
        yo[p] += eA * ((d0 + d1) + (d2 + d3)) + Dh * xh[p];
    }
}

// ---------------- gate with silu(z), rmsnorm ----------------
__global__ __launch_bounds__(256) void gatenorm_kernel(const float* __restrict__ nw) {
    int row = blockIdx.x;
    int t = threadIdx.x;
    const float4* yr = (const float4*)(g_y + (size_t)row * DINNER);
    const float4* zr = (const float4*)(g_zx + (size_t)row * DPROJ);
    float4 y4 = yr[t], z4 = zr[t];
    float g0 = y4.x * (z4.x / (1.f + __expf(-z4.x)));
    float g1 = y4.y * (z4.y / (1.f + __expf(-z4.y)));
    float g2 = y4.z * (z4.z / (1.f + __expf(-z4.z)));
    float g3 = y4.w * (z4.w / (1.f + __expf(-z4.w)));
    float ss = g0 * g0 + g1 * g1 + g2 * g2 + g3 * g3;
#pragma unroll
    for (int o = 16; o > 0; o >>= 1) ss += __shfl_xor_sync(0xffffffffu, ss, o);
    __shared__ float red[8];
    if ((t & 31) == 0) red[t >> 5] = ss;
    __syncthreads();
    float tot = red[0];
#pragma unroll
    for (int w = 1; w < 8; w++) tot += red[w];
    float sc = rsqrtf(tot / (float)DINNER + 1e-5f);
    const float4* n4p = (const float4*)nw;
    float4 n4 = n4p[t];
    float4 o4 = make_float4(g0 * sc * n4.x, g1 * sc * n4.y, g2 * sc * n4.z, g3 * sc * n4.w);
    *(float4*)(g_yf + (size_t)row * DINNER + t * 4) = o4;
}

// ---------------- launcher ----------------
extern "C" void kernel_launch(void* const* d_in, const int* in_sizes, int n_in,
                              void* d_out, int out_size) {
    (void)in_sizes; (void)n_in; (void)out_size;
    const float* x     = (const float*)d_in[0];
    const float* inw   = (const float*)d_in[1];
    const float* convw = (const float*)d_in[2];
    const float* convb = (const float*)d_in[3];
    const float* dtb   = (const float*)d_in[4];
    const float* alog  = (const float*)d_in[5];
    const float* Dv    = (const float*)d_in[6];
    const float* nw    = (const float*)d_in[7];
    const float* outw  = (const float*)d_in[8];
    float* out = (float*)d_out;

    float *zx, *yf;
    cudaGetSymbolAddress((void**)&zx, g_zx);
    cudaGetSymbolAddress((void**)&yf, g_yf);
    cudaFuncSetAttribute(chunk_kernel, cudaFuncAttributeMaxDynamicSharedMemorySize,
                         CHUNK_SMEM);

    const int M = B_SZ * SEQ;  // 16384

    // 1. in_proj GEMM: zx = x @ in_proj_w^T   [16384, 2192]  (bf16x3)
    tgemm_nt<<<dim3((DPROJ + 127) / 128, M / 128), 256>>>(x, inw, zx, M, DPROJ, DMODEL);
    // 2. dt: exact fp32 dot + softplus (independent of GEMM1)
    dt_kernel<<<M, 512>>>(x, inw, dtb);
    // 3. conv + silu
    conv_kernel<<<(B_SZ * SEQ * CONVDIM + 255) / 256, 256>>>(convw, convb);
    // 4. per-chunk scan of dt*A
    scan_kernel<<<B_SZ * NC * NHEADS, CHUNK>>>(alog);
    // 5. intra-chunk Y_diag + states
    chunk_kernel<<<B_SZ * NC * NHEADS, 256, CHUNK_SMEM>>>();
    // 6. inter-chunk recurrence
    recur_kernel<<<B_SZ * NHEADS, 256>>>();
    // 7. Y_off + D*x
    yoff_kernel<<<B_SZ * NC * NHEADS, 256>>>(Dv);
    // 8. gate + rmsnorm
    gatenorm_kernel<<<M, 256>>>(nw);
    // 9. out_proj GEMM: out = yf @ out_proj_w^T   [16384, 512]  (bf16x3)
    tgemm_nt<<<dim3(DMODEL / 128, M / 128), 256>>>(yf, outw, out, M, DMODEL, DINNER);
}